// round 13
// baseline (speedup 1.0000x reference)
#include <cuda_runtime.h>
#include <math.h>

#define NB 8
#define NS 2048
#define NE 1024
#define ND 64
#define NSPLIT 2

// ---------------------------------------------------------------------------
// Static device scratch (allocation-free).
// ---------------------------------------------------------------------------
__device__ float g_Q[NB * NS * ND];
__device__ float g_K[NB * NS * ND];
__device__ float g_V[NB * NS * ND];
__device__ int   g_js[NB * NS];
__device__ int   g_Nv[NB];
__device__ float g_Vmean[NB * ND];
__device__ float g_OP[NSPLIT][(size_t)NB * NS * ND];
__device__ float g_mP[NSPLIT][NB * NS];
__device__ float g_lP[NSPLIT][NB * NS];

// ---------------------------------------------------------------------------
// Packed f32x2 helpers (Blackwell FFMA2 path; PTX-only, base sm_100+ ISA).
// ---------------------------------------------------------------------------
typedef unsigned long long u64;
union U2 { u64 u; float2 f; };
union F4U { float4 v; u64 u[2]; };

__device__ __forceinline__ void ffma2(u64& d, u64 a, u64 b) {
    asm("fma.rn.f32x2 %0, %1, %2, %0;" : "+l"(d) : "l"(a), "l"(b));
}
__device__ __forceinline__ u64 mul2(u64 a, u64 b) {
    u64 r; asm("mul.rn.f32x2 %0, %1, %2;" : "=l"(r) : "l"(a), "l"(b));
    return r;
}
__device__ __forceinline__ u64 bcast2(float x) {
    u64 r; asm("mov.b64 %0, {%1, %1};" : "=l"(r) : "f"(x));
    return r;
}

// ----------------------------------------------------------------------------
// Kernel A: fused QKV projection, FFMA2 inner loop (acc packed along n).
// ----------------------------------------------------------------------------
__global__ __launch_bounds__(256) void qkv_kernel(
    const float* __restrict__ x,
    const float* __restrict__ Wq, const float* __restrict__ bq,
    const float* __restrict__ Wk, const float* __restrict__ bk,
    const float* __restrict__ Wv, const float* __restrict__ bv)
{
    __shared__ __align__(16) float As[16][68];
    __shared__ __align__(16) float Bs[16][196];   // 196 even -> rows 8B-aligned

    const int tid = threadIdx.x;
    const int tx = tid & 15;
    const int ty = tid >> 4;
    const int m0 = blockIdx.x * 64;

    u64 acc2[4][6];
    #pragma unroll
    for (int i = 0; i < 4; i++)
        #pragma unroll
        for (int j = 0; j < 6; j++) acc2[i][j] = 0ull;

    for (int k0 = 0; k0 < NE; k0 += 16) {
        #pragma unroll
        for (int r = 0; r < 4; r++) {
            int idx = tid + r * 256;
            int row = idx >> 4, col = idx & 15;
            As[col][row] = x[(size_t)(m0 + row) * NE + k0 + col];
        }
        #pragma unroll
        for (int r = 0; r < 12; r++) {
            int idx = tid + r * 256;
            int n = idx >> 4, kk = idx & 15;
            const float* W = (n < 64) ? Wq : ((n < 128) ? Wk : Wv);
            Bs[kk][n] = W[(size_t)(n & 63) * NE + k0 + kk];
        }
        __syncthreads();

        #pragma unroll
        for (int k = 0; k < 16; k++) {
            u64 a2[4], b2[6];
            #pragma unroll
            for (int i = 0; i < 4; i++) a2[i] = bcast2(As[k][ty * 4 + i]);
            #pragma unroll
            for (int j = 0; j < 6; j++)
                b2[j] = *(const u64*)&Bs[k][tx * 12 + 2 * j];
            #pragma unroll
            for (int i = 0; i < 4; i++)
                #pragma unroll
                for (int j = 0; j < 6; j++)
                    ffma2(acc2[i][j], a2[i], b2[j]);
        }
        __syncthreads();
    }

    #pragma unroll
    for (int i = 0; i < 4; i++) {
        int m = m0 + ty * 4 + i;
        #pragma unroll
        for (int j6 = 0; j6 < 6; j6++) {
            U2 t; t.u = acc2[i][j6];
            #pragma unroll
            for (int h = 0; h < 2; h++) {
                int n = tx * 12 + 2 * j6 + h;
                float val = (h ? t.f.y : t.f.x);
                float bias = (n < 64) ? bq[n] : ((n < 128) ? bk[n - 64] : bv[n - 128]);
                float v = val + bias;
                if (n < 64)       g_Q[(size_t)m * ND + n] = v;
                else if (n < 128) g_K[(size_t)m * ND + (n - 64)] = v;
                else              g_V[(size_t)m * ND + (n - 128)] = v;
            }
        }
    }
}

// ----------------------------------------------------------------------------
// Kernel P: per-batch prep (mask compaction + V column-mean). Unchanged.
// ----------------------------------------------------------------------------
__global__ __launch_bounds__(256) void prep_kernel(const int* __restrict__ mask)
{
    const int b = blockIdx.x;
    const int tid = threadIdx.x;
    __shared__ int ps[257];
    __shared__ float vred[256];

    const int base = tid * 8;
    int loc[8], cnt = 0;
    #pragma unroll
    for (int u = 0; u < 8; u++) {
        loc[u] = mask[b * NS + base + u];
        cnt += (loc[u] != 0);
    }
    ps[tid + 1] = cnt;
    __syncthreads();
    if (tid == 0) {
        ps[0] = 0;
        for (int t = 1; t <= 256; t++) ps[t] += ps[t - 1];
    }
    __syncthreads();

    int pos = ps[tid];
    #pragma unroll
    for (int u = 0; u < 8; u++) {
        if (loc[u] != 0) g_js[b * NS + pos++] = base + u;
    }
    if (tid == 0) g_Nv[b] = ps[256];

    const int d = tid & 63;
    const int seg = tid >> 6;
    float s = 0.f;
    const float* Vb = &g_V[(size_t)b * NS * ND];
    for (int r = seg * 512; r < seg * 512 + 512; r++)
        s += Vb[(size_t)r * ND + d];
    vred[tid] = s;
    __syncthreads();
    if (tid < 64) {
        float t = vred[tid] + vred[tid + 64] + vred[tid + 128] + vred[tid + 192];
        g_Vmean[b * ND + tid] = t * (1.0f / NS);
    }
}

// ----------------------------------------------------------------------------
// Kernel B: split-KV flash attention, FFMA2 inner loops.
//   QK^T packs the reduction dim (float4 = two f32x2 pairs; horizontal add
//   once per tile). P@V packs the output dim (Vs rows are d-contiguous).
// ----------------------------------------------------------------------------
__global__ __launch_bounds__(256) void attn_kernel()
{
    extern __shared__ __align__(16) float fsm[];
    float* Qs   = fsm;                  // 64*68
    float* Ks   = Qs + 64 * 68;         // 64*68 (aliased by Ps)
    float* Vs   = Ks + 64 * 68;         // 64*68
    float* red  = Vs + 64 * 68;         // 64*16
    float* m_st = red + 64 * 16;        // 64
    float* l_st = m_st + 64;            // 64
    float* al_s = l_st + 64;            // 64
    int*   js_s = (int*)(al_s + 64);    // 64
    float* Ps   = Ks;                   // alias

    const int tid = threadIdx.x;
    const int tx = tid & 15;
    const int ty = tid >> 4;
    const int b  = blockIdx.y;
    const int i0 = blockIdx.x * 64;
    const int sp = blockIdx.z;

    const int Nv = g_Nv[b];
    const int ntiles = (Nv + 63) >> 6;

    // Binary search: first compacted position with index >= i0.
    int lo = 0, hi = Nv;
    while (lo < hi) {
        int mid = (lo + hi) >> 1;
        if (g_js[b * NS + mid] < i0) lo = mid + 1; else hi = mid;
    }
    const int jt0 = lo >> 6;
    const int nav = ntiles - jt0;
    const int nh  = (nav + 1) >> 1;
    const int t_begin = jt0 + sp * nh;
    const int t_end   = sp ? ntiles : (jt0 + nh);

    if (tid < 64) { m_st[tid] = -INFINITY; l_st[tid] = 0.f; }

    #pragma unroll
    for (int p = 0; p < 4; p++) {
        int r = p * 16 + ty;
        float4 q = *(const float4*)&g_Q[((size_t)b * NS + i0 + r) * ND + tx * 4];
        q.x *= 0.125f; q.y *= 0.125f; q.z *= 0.125f; q.w *= 0.125f;
        *(float4*)&Qs[r * 68 + tx * 4] = q;
    }

    // Output accumulator: packed along d (2 pairs per thread).
    u64 o2[4][2];
    #pragma unroll
    for (int i = 0; i < 4; i++) { o2[i][0] = 0ull; o2[i][1] = 0ull; }

    const int gi_base = i0 + ty * 4;

    for (int jt = t_begin; jt < t_end; jt++) {
        const int j0c = jt * 64;
        __syncthreads();

        if (tid < 64) {
            int c = j0c + tid;
            js_s[tid] = (c < Nv) ? g_js[b * NS + c] : -1;
        }
        __syncthreads();

        #pragma unroll
        for (int p = 0; p < 4; p++) {
            int r = p * 16 + ty;
            int src = js_s[r];
            if (src < 0) src = 0;
            *(float4*)&Ks[r * 68 + tx * 4] =
                *(const float4*)&g_K[((size_t)b * NS + src) * ND + tx * 4];
            *(float4*)&Vs[r * 68 + tx * 4] =
                *(const float4*)&g_V[((size_t)b * NS + src) * ND + tx * 4];
        }
        __syncthreads();

        // ---- S = Q @ K^T, packed along the reduction dim ----
        u64 s2[4][4];
        #pragma unroll
        for (int i = 0; i < 4; i++)
            #pragma unroll
            for (int j = 0; j < 4; j++) s2[i][j] = 0ull;

        #pragma unroll
        for (int d = 0; d < 64; d += 4) {
            F4U qa[4], ka[4];
            #pragma unroll
            for (int i = 0; i < 4; i++)
                qa[i].v = *(float4*)&Qs[(ty * 4 + i) * 68 + d];
            #pragma unroll
            for (int j = 0; j < 4; j++)
                ka[j].v = *(float4*)&Ks[(tx * 4 + j) * 68 + d];
            #pragma unroll
            for (int i = 0; i < 4; i++)
                #pragma unroll
                for (int j = 0; j < 4; j++) {
                    ffma2(s2[i][j], qa[i].u[0], ka[j].u[0]);
                    ffma2(s2[i][j], qa[i].u[1], ka[j].u[1]);
                }
        }

        // Horizontal add + mask.
        float s[4][4];
        #pragma unroll
        for (int i = 0; i < 4; i++) {
            int gi = gi_base + i;
            #pragma unroll
            for (int j = 0; j < 4; j++) {
                U2 t; t.u = s2[i][j];
                bool valid = (js_s[tx * 4 + j] >= gi);
                s[i][j] = valid ? (t.f.x + t.f.y) : -1e22f;
            }
        }

        // ---- row max ----
        #pragma unroll
        for (int i = 0; i < 4; i++) {
            float pm = fmaxf(fmaxf(s[i][0], s[i][1]), fmaxf(s[i][2], s[i][3]));
            red[(ty * 4 + i) * 16 + tx] = pm;
        }
        __syncthreads();
        if (tid < 64) {
            const float* rr = &red[tid * 16];
            float mx = rr[0];
            #pragma unroll
            for (int t = 1; t < 16; t++) mx = fmaxf(mx, rr[t]);
            float mo = m_st[tid];
            float mn = fmaxf(mo, mx);
            m_st[tid] = mn;
            al_s[tid] = __expf(mo - mn);
        }
        __syncthreads();

        // ---- p = exp(s - m), write P (aliases K), rescale O, row sums ----
        #pragma unroll
        for (int i = 0; i < 4; i++) {
            int r = ty * 4 + i;
            float mn = m_st[r];
            float a  = al_s[r];
            float psum = 0.f;
            #pragma unroll
            for (int j = 0; j < 4; j++) {
                float p = __expf(s[i][j] - mn);
                Ps[r * 68 + tx * 4 + j] = p;
                psum += p;
            }
            u64 a2 = bcast2(a);
            o2[i][0] = mul2(o2[i][0], a2);
            o2[i][1] = mul2(o2[i][1], a2);
            red[r * 16 + tx] = psum;
        }
        __syncthreads();
        if (tid < 64) {
            const float* rr = &red[tid * 16];
            float sum = 0.f;
            #pragma unroll
            for (int t = 0; t < 16; t++) sum += rr[t];
            l_st[tid] = l_st[tid] * al_s[tid] + sum;
        }

        // ---- O += P @ V, packed along d ----
        #pragma unroll
        for (int cc = 0; cc < 64; cc += 4) {
            float4 pa[4];
            F4U va[4];
            #pragma unroll
            for (int i = 0; i < 4; i++)
                pa[i] = *(float4*)&Ps[(ty * 4 + i) * 68 + cc];
            #pragma unroll
            for (int q = 0; q < 4; q++)
                va[q].v = *(float4*)&Vs[(cc + q) * 68 + tx * 4];
            #pragma unroll
            for (int i = 0; i < 4; i++) {
                const float* pf = (const float*)&pa[i];
                #pragma unroll
                for (int q = 0; q < 4; q++) {
                    u64 p2 = bcast2(pf[q]);
                    ffma2(o2[i][0], p2, va[q].u[0]);
                    ffma2(o2[i][1], p2, va[q].u[1]);
                }
            }
        }
    }

    __syncthreads();  // final m_st/l_st visible (also required if 0 iterations)

    // Emit partials (unnormalized O, m, l).
    #pragma unroll
    for (int i = 0; i < 4; i++) {
        int r = ty * 4 + i;
        U2 t0, t1; t0.u = o2[i][0]; t1.u = o2[i][1];
        float4 v;
        v.x = t0.f.x; v.y = t0.f.y; v.z = t1.f.x; v.w = t1.f.y;
        *(float4*)&g_OP[sp][((size_t)b * NS + i0 + r) * ND + tx * 4] = v;
    }
    if (tid < 64) {
        g_mP[sp][b * NS + i0 + tid] = m_st[tid];
        g_lP[sp][b * NS + i0 + tid] = l_st[tid];
    }
}

// ----------------------------------------------------------------------------
// Kernel M: merge the two split-KV partials. Unchanged.
// ----------------------------------------------------------------------------
__global__ __launch_bounds__(256) void merge_kernel(float* __restrict__ out)
{
    const int idx = blockIdx.x * 256 + threadIdx.x;
    const int row = idx >> 4;
    const int c   = (idx & 15) * 4;
    const int b   = row >> 11;

    const float m0 = g_mP[0][row];
    const float m1 = g_mP[1][row];
    const float m  = fmaxf(m0, m1);

    float4 r;
    if (m <= -1e21f) {
        r = *(const float4*)&g_Vmean[b * ND + c];
    } else {
        const float e0 = __expf(m0 - m);
        const float e1 = __expf(m1 - m);
        const float l  = g_lP[0][row] * e0 + g_lP[1][row] * e1;
        const float inv = 1.0f / l;
        const float4 a  = *(const float4*)&g_OP[0][(size_t)row * ND + c];
        const float4 bb = *(const float4*)&g_OP[1][(size_t)row * ND + c];
        r.x = (a.x * e0 + bb.x * e1) * inv;
        r.y = (a.y * e0 + bb.y * e1) * inv;
        r.z = (a.z * e0 + bb.z * e1) * inv;
        r.w = (a.w * e0 + bb.w * e1) * inv;
    }
    *(float4*)&out[(size_t)row * ND + c] = r;
}

// ----------------------------------------------------------------------------
// Launch: QKV -> prep -> split-KV attention -> merge.
// ----------------------------------------------------------------------------
extern "C" void kernel_launch(void* const* d_in, const int* in_sizes, int n_in,
                              void* d_out, int out_size)
{
    const float* x    = (const float*)d_in[0];
    const int*   mask = (const int*)  d_in[1];
    const float* Wq   = (const float*)d_in[2];
    const float* bq   = (const float*)d_in[3];
    const float* Wk   = (const float*)d_in[4];
    const float* bk   = (const float*)d_in[5];
    const float* Wv   = (const float*)d_in[6];
    const float* bv   = (const float*)d_in[7];
    float* out = (float*)d_out;

    qkv_kernel<<<(NB * NS) / 64, 256>>>(x, Wq, bq, Wk, bk, Wv, bv);
    prep_kernel<<<NB, 256>>>(mask);

    const int ATTN_SMEM = (3 * 64 * 68 + 64 * 16 + 3 * 64) * 4 + 64 * 4;
    cudaFuncSetAttribute(attn_kernel,
                         cudaFuncAttributeMaxDynamicSharedMemorySize, ATTN_SMEM);
    dim3 grid(NS / 64, NB, NSPLIT);
    attn_kernel<<<grid, 256, ATTN_SMEM>>>();

    merge_kernel<<<(NB * NS * ND / 4) / 256, 256>>>(out);
}